// round 5
// baseline (speedup 1.0000x reference)
#include <cuda_runtime.h>
#include <cstdint>

#define BB 32
#define AA 8400
#define AA_PAD 8448
#define NCLS 80
#define KTOP 1024
#define GG 32
#define NSUP 16
#define MAX_DET 300
#define NBIN 258
#define CAND 2048

typedef unsigned long long u64;

// ---------------- static device scratch ----------------
__device__ u64 d_keys[BB * AA];
__device__ int d_cls[BB * AA];

// monotonic float->u32 map (total order matching float order)
__device__ __forceinline__ unsigned f2sortable(float f) {
    unsigned b = __float_as_uint(f);
    return (b & 0x80000000u) ? ~b : (b | 0x80000000u);
}
__device__ __forceinline__ float sortable2f(unsigned s) {
    return __uint_as_float((s & 0x80000000u) ? (s ^ 0x80000000u) : ~s);
}

// ---------------- 1. decode: conf/cls per anchor -> 64-bit keys ----------------
__global__ void decode_kernel(const float* __restrict__ preds) {
    int b = blockIdx.y;
    int a = blockIdx.x * blockDim.x + threadIdx.x;
    if (a >= AA) return;
    const float* p = preds + (size_t)b * 84 * AA;
    float best = p[4 * AA + a];
    int cls = 0;
    #pragma unroll 8
    for (int c = 1; c < NCLS; c++) {
        float v = p[(4 + c) * AA + a];
        if (v > best) { best = v; cls = c; }   // first-max semantics (jnp.argmax)
    }
    float conf = (best > 0.25f) ? best : 0.0f;
    unsigned cbits = __float_as_uint(conf);
    // tie-break: equal conf -> lower anchor index wins (larger low bits)
    d_keys[b * AA + a] = ((u64)cbits << 32) | (unsigned)(AA - 1 - a);
    d_cls[b * AA + a] = cls;
}

// ---------------- dynamic smem layout (bytes) ----------------
#define OFF_SORT   0                      // u64[2048]            16384
#define OFF_SBOX   16384                  // float4[1024]         16384
#define OFF_BOX    32768                  // float4[1024]         16384
#define OFF_CONF   49152                  // float[1024]           4096
#define OFF_CLS    53248                  // int[1024]             4096
#define OFF_HIST   57344                  // int[258] (+pad)       1088
#define OFF_SUB    58432                  // int[256]              1024
#define OFF_CNT    59456                  // int[80] (+pad)         384
#define OFF_OFFS   59840                  // int[80] (+pad)         384
#define OFF_CUR    60224                  // int[80] (+pad)         384
#define OFF_ITEMS  60608                  // int[1024]             4096
#define OFF_KEEPW  64704                  // unsigned[32] (+pad)    256
#define OFF_MASK   64960                  // unsigned[1024*33]   135168
#define SMEM_TOTAL (OFF_MASK + KTOP * 33 * 4)   // 200128 bytes

// ---------------- 2. fused: select -> sparse mask -> scan -> match ----------------
__global__ void __launch_bounds__(256) fused_kernel(
    const float* __restrict__ preds,
    const float* __restrict__ gt_boxes,
    const int*   __restrict__ gt_cls,
    const int*   __restrict__ gt_mask,
    const int*   __restrict__ cat_to_super,
    float* __restrict__ out)
{
    extern __shared__ unsigned char smraw[];
    u64*      s_sort = (u64*)     (smraw + OFF_SORT);
    float4*   s_sbox = (float4*)  (smraw + OFF_SBOX);
    float4*   s_box  = (float4*)  (smraw + OFF_BOX);
    float*    s_conf = (float*)   (smraw + OFF_CONF);
    int*      s_cls  = (int*)     (smraw + OFF_CLS);
    int*      s_hist = (int*)     (smraw + OFF_HIST);
    int*      s_sub  = (int*)     (smraw + OFF_SUB);
    int*      s_cnt  = (int*)     (smraw + OFF_CNT);
    int*      s_offs = (int*)     (smraw + OFF_OFFS);
    int*      s_cur  = (int*)     (smraw + OFF_CUR);
    int*      s_items= (int*)     (smraw + OFF_ITEMS);
    unsigned* s_keepw= (unsigned*)(smraw + OFF_KEEPW);
    unsigned* s_mask = (unsigned*)(smraw + OFF_MASK);

    __shared__ int sh_cstar, sh_above, sh_scnt, sh_npred;
    __shared__ u64 sh_thr;
    __shared__ u64 sbest[GG];
    __shared__ float4 sgt[GG];
    __shared__ int sgc[GG];

    int b   = blockIdx.x;
    int tid = threadIdx.x;                 // 256 threads
    int lane = tid & 31;
    int wid  = tid >> 5;
    const u64* keys = d_keys + (size_t)b * AA;

    // ---- A1: level-1 histogram of key high-16 ----
    for (int i = tid; i < NBIN; i += 256) s_hist[i] = 0;
    for (int i = tid; i < KTOP * 33; i += 256) s_mask[i] = 0;   // zero mask early
    __syncthreads();
    for (int i = tid; i < AA; i += 256) {
        int bin = (int)(keys[i] >> 48) - 15999;
        if (bin < 0) bin = 0;              // conf==0
        atomicAdd(&s_hist[bin], 1);
    }
    __syncthreads();

    // ---- A2: level-1 cutoff bin ----
    if (tid == 0) {
        int cum = 0, cstar = 1, above = -1;
        for (int c = NBIN - 1; c >= 1; c--) {
            if (cum + s_hist[c] >= KTOP) { cstar = c; above = cum; break; }
            cum += s_hist[c];
        }
        if (above < 0) { cstar = 1; above = cum - s_hist[1]; }
        sh_cstar = cstar; sh_above = above;
        sh_scnt = 0;
    }
    for (int i = tid; i < 256; i += 256) s_sub[i] = 0;
    __syncthreads();

    // ---- A3: level-2 sub-histogram within cutoff bin ----
    {
        int target = sh_cstar + 15999;
        for (int i = tid; i < AA; i += 256) {
            u64 k = keys[i];
            if ((int)(k >> 48) == target)
                atomicAdd(&s_sub[(int)(k >> 40) & 0xFF], 1);
        }
    }
    __syncthreads();
    if (tid == 0) {
        int above = sh_above, cum = 0, sstar = 0;
        for (int s = 255; s >= 0; s--) {
            cum += s_sub[s];
            if (above + cum >= KTOP) { sstar = s; break; }
        }
        unsigned cb_min = ((unsigned)(sh_cstar + 15999) << 16) | ((unsigned)sstar << 8);
        sh_thr = (u64)cb_min << 32;        // candidates in [1024, ~1064] -> fits CAND
    }
    for (int i = tid; i < CAND; i += 256) s_sort[i] = 0ull;
    __syncthreads();

    // ---- A4: compact candidates (warp-aggregated atomic) ----
    {
        u64 thr = sh_thr;
        for (int base = 0; base < AA_PAD; base += 256) {
            int i = base + tid;
            u64 k = (i < AA) ? keys[i] : 0ull;
            bool pred = (i < AA) && (k >= thr);
            unsigned ball = __ballot_sync(0xffffffffu, pred);
            int cnt = __popc(ball);
            int pos0 = 0;
            if (lane == 0 && cnt) pos0 = atomicAdd(&sh_scnt, cnt);
            pos0 = __shfl_sync(0xffffffffu, pos0, 0);
            if (pred) {
                int pos = pos0 + __popc(ball & ((1u << lane) - 1));
                if (pos < CAND) s_sort[pos] = k;
            }
        }
    }
    __syncthreads();

    // ---- A5: descending bitonic sort of 2048 unique keys ----
    for (int k = 2; k <= CAND; k <<= 1) {
        for (int j = k >> 1; j > 0; j >>= 1) {
            for (int t = tid; t < CAND; t += 256) {
                int ixj = t ^ j;
                if (ixj > t) {
                    u64 x = s_sort[t], y = s_sort[ixj];
                    bool up = ((t & k) == 0);
                    if (up ? (x < y) : (x > y)) { s_sort[t] = y; s_sort[ixj] = x; }
                }
            }
            __syncthreads();
        }
    }

    // ---- A6: build selected arrays in smem ----
    for (int r = tid; r < KTOP; r += 256) {
        u64 key = s_sort[r];
        float conf = __uint_as_float((unsigned)(key >> 32));
        int a = AA - 1 - (int)(key & 0xFFFFFFFFu);
        const float* p = preds + (size_t)b * 84 * AA;
        float cx = p[0 * AA + a], cy = p[1 * AA + a];
        float w  = p[2 * AA + a], h  = p[3 * AA + a];
        float x1 = cx - 0.5f * w, y1 = cy - 0.5f * h;
        float x2 = cx + 0.5f * w, y2 = cy + 0.5f * h;
        int cls = d_cls[b * AA + a];
        float sh = (float)cls * 7680.0f;
        s_conf[r] = conf;
        s_cls[r]  = cls;
        s_box[r]  = make_float4(x1, y1, x2, y2);
        s_sbox[r] = make_float4(x1 + sh, y1 + sh, x2 + sh, y2 + sh);
    }
    // class CSR counters
    for (int c = tid; c < NCLS; c += 256) s_cnt[c] = 0;
    __syncthreads();

    // ---- B: sparse same-class pair mask ----
    for (int r = tid; r < KTOP; r += 256) atomicAdd(&s_cnt[s_cls[r]], 1);
    __syncthreads();
    if (tid == 0) {
        int acc = 0;
        for (int c = 0; c < NCLS; c++) { s_offs[c] = acc; s_cur[c] = acc; acc += s_cnt[c]; }
    }
    __syncthreads();
    for (int r = tid; r < KTOP; r += 256) {
        int p = atomicAdd(&s_cur[s_cls[r]], 1);
        s_items[p] = r;
    }
    __syncthreads();
    // cross-class pairs: shift difference >= 7680 vs coords <= ~800 -> inter==0 exactly
    // -> iou==0 -> bit never set. Only same-class pairs computed, bit-exact vs reference.
    for (int c = wid; c < NCLS; c += 8) {
        int n = s_cnt[c], off = s_offs[c];
        for (int a2 = 0; a2 < n - 1; a2++) {
            int i = s_items[off + a2];
            float4 bi = s_sbox[i];
            float ai = (bi.z - bi.x) * (bi.w - bi.y);
            for (int b2 = a2 + 1 + lane; b2 < n; b2 += 32) {
                int j = s_items[off + b2];
                float4 bj = s_sbox[j];
                float lx = fmaxf(bi.x, bj.x), ly = fmaxf(bi.y, bj.y);
                float rx = fminf(bi.z, bj.z), ry = fminf(bi.w, bj.w);
                float iw = fmaxf(rx - lx, 0.0f), ih = fmaxf(ry - ly, 0.0f);
                float inter = iw * ih;
                float aj = (bj.z - bj.x) * (bj.w - bj.y);
                float denom = ai + aj - inter + 1e-9f;
                float iou = __fdiv_rn(inter, denom);
                if (iou > 0.45f) {
                    int p = min(i, j), q = max(i, j);
                    atomicOr(&s_mask[p * 33 + (q >> 5)], 1u << (q & 31));
                }
            }
        }
    }
    __syncthreads();

    // ---- C: serial greedy NMS scan (warp 0; diag in registers) ----
    if (tid < 32) {
        unsigned vw = 0;
        #pragma unroll
        for (int i = 0; i < 32; i++)
            vw |= (s_conf[lane * 32 + i] > 0.0f ? 1u : 0u) << i;

        unsigned acc = 0, keep_local = 0;
        for (int c = 0; c < 32; c++) {
            unsigned base = __shfl_sync(0xffffffffu, acc, c);
            unsigned valc = __shfl_sync(0xffffffffu, vw, c);
            unsigned diag[32];
            #pragma unroll
            for (int j = 0; j < 32; j++) diag[j] = s_mask[(c * 32 + j) * 33 + c];
            unsigned cur = base, kbits = 0;
            #pragma unroll
            for (int j = 0; j < 32; j++) {
                if (((valc >> j) & 1u) && !((cur >> j) & 1u)) {
                    cur |= diag[j];
                    kbits |= (1u << j);
                }
            }
            unsigned t2 = kbits;
            while (t2) {
                int j = __ffs(t2) - 1; t2 &= t2 - 1;
                acc |= s_mask[(c * 32 + j) * 33 + lane];
            }
            if (lane == c) keep_local = kbits;
        }
        // trim to MAX_DET
        int myc = __popc(keep_local);
        int pre = myc;
        #pragma unroll
        for (int d = 1; d < 32; d <<= 1) {
            int v = __shfl_up_sync(0xffffffffu, pre, d);
            if (lane >= d) pre += v;
        }
        pre -= myc;
        unsigned kw2 = 0, tmp = keep_local;
        while (tmp) {
            int p = __ffs(tmp) - 1; tmp &= tmp - 1;
            int rank = pre + __popc(keep_local & ((1u << p) - 1));
            if (rank < MAX_DET) kw2 |= (1u << p);
        }
        s_keepw[lane] = kw2;
    }
    // ---- D: GT matching + stats ----
    if (tid < GG) {
        const float* gb = gt_boxes + (size_t)(b * GG + tid) * 4;
        sgt[tid] = make_float4(gb[0], gb[1], gb[2], gb[3]);
        sgc[tid] = gt_cls[b * GG + tid];
        sbest[tid] = 0ull;
    }
    if (tid == 0) sh_npred = 0;
    __syncthreads();

    bool  pv4[4];
    float4 bx4[4];
    int   cls4[4];
    float ap4[4];
    int cntpv = 0;
    #pragma unroll
    for (int u = 0; u < 4; u++) {
        int i = tid + u * 256;
        bool kb = (s_keepw[i >> 5] >> (i & 31)) & 1u;
        float conf = s_conf[i];
        bool pv = kb && (conf > 0.5f);
        pv4[u] = pv;
        if (pv) cntpv++;
        bx4[u] = s_box[i];
        cls4[u] = s_cls[i];
        ap4[u] = (bx4[u].z - bx4[u].x) * (bx4[u].w - bx4[u].y);
    }
    {
        int red = cntpv;
        #pragma unroll
        for (int d = 16; d; d >>= 1) red += __shfl_xor_sync(0xffffffffu, red, d);
        if (lane == 0) atomicAdd(&sh_npred, red);
    }
    for (int g = 0; g < GG; g++) {
        float4 gb = sgt[g];
        int gc = sgc[g];
        float ag = (gb.z - gb.x) * (gb.w - gb.y);
        u64 best = 0ull;
        #pragma unroll
        for (int u = 0; u < 4; u++) {
            int i = tid + u * 256;
            float4 bx = bx4[u];
            float lx = fmaxf(bx.x, gb.x), ly = fmaxf(bx.y, gb.y);
            float rx = fminf(bx.z, gb.z), ry = fminf(bx.w, gb.w);
            float iw = fmaxf(rx - lx, 0.0f), ih = fmaxf(ry - ly, 0.0f);
            float inter = iw * ih;
            float iou = __fdiv_rn(inter, ap4[u] + ag - inter + 1e-9f);
            float ioum = (pv4[u] && cls4[u] == gc) ? iou : -1.0f;
            u64 key = ((u64)f2sortable(ioum) << 32) | (unsigned)(KTOP - 1 - i);
            if (key > best) best = key;
        }
        #pragma unroll
        for (int d = 16; d; d >>= 1) {
            u64 o = __shfl_xor_sync(0xffffffffu, best, d);
            if (o > best) best = o;
        }
        if (lane == 0) atomicMax(&sbest[g], best);
    }
    __syncthreads();

    if (tid == 0) {
        float sum_iou = 0.0f, sum_conf = 0.0f;
        int n_hit = 0, n_gt = 0;
        for (int g = 0; g < GG; g++) {
            int gm = gt_mask[b * GG + g];
            if (gm != 0) n_gt++;
            u64 key = sbest[g];
            float biou = sortable2f((unsigned)(key >> 32));
            int pidx = KTOP - 1 - (int)(key & 0xFFFFFFFFu);
            bool hit = (biou > 0.6f) && (gm != 0);
            if (hit) {
                n_hit++;
                sum_iou += biou;
                sum_conf += s_conf[pidx];
            }
        }
        float fh = (float)n_hit;
        float mean_iou  = __fdiv_rn(sum_iou, fmaxf(fh, 1.0f));
        float mean_conf = (n_hit > 0) ? __fdiv_rn(sum_conf, fmaxf(fh, 1.0f)) : 1.0f;
        float correct   = __fdiv_rn(fh, fmaxf((float)n_gt, 1.0f));

        float cc[NCLS];
        float sc[NSUP];
        for (int c = 0; c < NCLS; c++) cc[c] = 0.0f;
        for (int s = 0; s < NSUP; s++) sc[s] = 0.0f;
        for (int g = 0; g < GG; g++) {
            float gm = (gt_mask[b * GG + g] != 0) ? 1.0f : 0.0f;
            int c = gt_cls[b * GG + g];
            cc[c] += gm;
            sc[cat_to_super[c]] += gm;
        }
        float bc = cc[0]; int mfc = 0;
        for (int c = 1; c < NCLS; c++) if (cc[c] > bc) { bc = cc[c]; mfc = c; }
        float bs = sc[0]; int mfs = 0;
        for (int s = 1; s < NSUP; s++) if (sc[s] > bs) { bs = sc[s]; mfs = s; }

        float r0, r1, r2, r3, r4;
        if (n_gt == 0) {
            if (sh_npred == 0) { r0 = 1.0f; r1 = 1.0f; r2 = -1.0f; r3 = -1.0f; r4 = 1.0f; }
            else               { r0 = 0.0f; r1 = 1.0f; r2 = -2.0f; r3 = -2.0f; r4 = 0.0f; }
        } else {
            r0 = mean_iou; r1 = mean_conf; r2 = (float)mfc; r3 = (float)mfs; r4 = correct;
        }
        float* o = out + b * 5;
        o[0] = r0; o[1] = r1; o[2] = r2; o[3] = r3; o[4] = r4;
    }
}

// ---------------- launcher ----------------
extern "C" void kernel_launch(void* const* d_in, const int* in_sizes, int n_in,
                              void* d_out, int out_size) {
    const float* preds        = (const float*)d_in[0];
    const float* gt_boxes     = (const float*)d_in[1];
    const int*   gt_cls       = (const int*)d_in[2];
    const int*   gt_mask      = (const int*)d_in[3];
    const int*   cat_to_super = (const int*)d_in[4];
    float* out = (float*)d_out;

    (void)in_sizes; (void)n_in; (void)out_size;

    cudaFuncSetAttribute(fused_kernel, cudaFuncAttributeMaxDynamicSharedMemorySize,
                         SMEM_TOTAL);

    decode_kernel<<<dim3((AA + 255) / 256, BB), 256>>>(preds);
    fused_kernel<<<BB, 256, SMEM_TOTAL>>>(preds, gt_boxes, gt_cls, gt_mask,
                                          cat_to_super, out);
}

// round 6
// speedup vs baseline: 1.2095x; 1.2095x over previous
#include <cuda_runtime.h>
#include <cstdint>

#define BB 32
#define AA 8400
#define AA_PAD 8448
#define NCLS 80
#define KTOP 1024
#define GG 32
#define NSUP 16
#define MAX_DET 300
#define KW (KTOP/32)
#define NBIN2 4098           // bin0 = conf==0, bins 1..4097 = (cbits>>12) - 0x3E800 + 1
#define NBIN2_PAD 4112
#define CAND 2048

typedef unsigned long long u64;

// ---------------- static device scratch ----------------
__device__ u64      d_keys[BB * AA];
__device__ int      d_cls[BB * AA];
__device__ int      d_hist[BB * NBIN2_PAD];
__device__ float    d_sel_conf[BB * KTOP];
__device__ int      d_sel_cls[BB * KTOP];
__device__ float4   d_sel_box[BB * KTOP];
__device__ float4   d_sel_sbox[BB * KTOP];
__device__ int      d_items[BB * KTOP];
__device__ int      d_ccnt[BB * NCLS];
__device__ int      d_coff[BB * NCLS];
__device__ int      d_nvalid[BB];
__device__ unsigned d_keepw[BB * KW];

__device__ __forceinline__ unsigned f2sortable(float f) {
    unsigned b = __float_as_uint(f);
    return (b & 0x80000000u) ? ~b : (b | 0x80000000u);
}
__device__ __forceinline__ float sortable2f(unsigned s) {
    return __uint_as_float((s & 0x80000000u) ? (s ^ 0x80000000u) : ~s);
}

// ---------------- 0. zero histograms ----------------
__global__ void init_hist_kernel() {
    int i = blockIdx.x * blockDim.x + threadIdx.x;
    if (i < BB * NBIN2_PAD) d_hist[i] = 0;
}

// ---------------- 1. decode: conf/cls -> keys + fine histogram ----------------
__global__ void decode_kernel(const float* __restrict__ preds) {
    __shared__ int hh[NBIN2];
    int b = blockIdx.y;
    int a = blockIdx.x * blockDim.x + threadIdx.x;
    for (int i = threadIdx.x; i < NBIN2; i += blockDim.x) hh[i] = 0;
    __syncthreads();
    if (a < AA) {
        const float* p = preds + (size_t)b * 84 * AA;
        float best = p[4 * AA + a];
        int cls = 0;
        #pragma unroll 8
        for (int c = 1; c < NCLS; c++) {
            float v = p[(4 + c) * AA + a];
            if (v > best) { best = v; cls = c; }   // first-max (jnp.argmax)
        }
        float conf = (best > 0.25f) ? best : 0.0f;
        unsigned cbits = __float_as_uint(conf);
        d_keys[b * AA + a] = ((u64)cbits << 32) | (unsigned)(AA - 1 - a);
        d_cls[b * AA + a] = cls;
        int bin = (conf == 0.0f) ? 0 : (int)(cbits >> 12) - 0x3E800 + 1;  // 1..4097
        atomicAdd(&hh[bin], 1);
    }
    __syncthreads();
    for (int i = threadIdx.x; i < NBIN2; i += blockDim.x)
        if (hh[i]) atomicAdd(&d_hist[b * NBIN2_PAD + i], hh[i]);
}

// ---------------- 2. select: suffix-scan cutoff -> compact -> sort -> gather+CSR ----------------
#define BINS_PER_T 5
__global__ void __launch_bounds__(1024) select_kernel(const float* __restrict__ preds) {
    __shared__ int  s_hist[NBIN2];
    __shared__ int  s_ps[1024];
    __shared__ u64  s_sort[CAND];
    __shared__ int  s_cnt[NCLS], s_offs[NCLS], s_cur[NCLS];
    __shared__ int  sh_cstar, sh_scnt, sh_nvalid;
    __shared__ u64  sh_thr;

    int b   = blockIdx.x;
    int tid = threadIdx.x;
    int lane = tid & 31;
    const u64* keys = d_keys + (size_t)b * AA;

    for (int i = tid; i < NBIN2; i += 1024) s_hist[i] = d_hist[b * NBIN2_PAD + i];
    if (tid == 0) { sh_cstar = 1; sh_scnt = 0; }
    __syncthreads();

    // partial sums (skip bin 0), then Hillis-Steele suffix scan
    {
        int sum = 0;
        #pragma unroll
        for (int k = 0; k < BINS_PER_T; k++) {
            int c = tid * BINS_PER_T + k;
            if (c >= 1 && c < NBIN2) sum += s_hist[c];
        }
        s_ps[tid] = sum;
    }
    __syncthreads();
    for (int d = 1; d < 1024; d <<= 1) {
        int v = (tid + d < 1024) ? s_ps[tid + d] : 0;
        __syncthreads();
        s_ps[tid] += v;
        __syncthreads();
    }
    // unique firing thread: suffix(me) >= K, suffix(me+1) < K
    {
        int sfx  = s_ps[tid];
        int nxt  = (tid + 1 < 1024) ? s_ps[tid + 1] : 0;
        if (sfx >= KTOP && nxt < KTOP) {
            int cum = nxt, cstar = 1;
            for (int c = min(tid * BINS_PER_T + BINS_PER_T - 1, NBIN2 - 1);
                 c >= tid * BINS_PER_T; c--) {
                if (c < 1) break;
                cum += s_hist[c];
                if (cum >= KTOP) { cstar = c; break; }
            }
            sh_cstar = cstar;
        }
        if (tid == 0) sh_nvalid = min(s_ps[0], KTOP);
    }
    __syncthreads();
    if (tid == 0) {
        unsigned thrhi = ((unsigned)(sh_cstar - 1 + 0x3E800)) << 12;  // min cbits in bin cstar
        sh_thr = (u64)thrhi << 32;
    }
    for (int i = tid; i < CAND; i += 1024) s_sort[i] = 0ull;
    __syncthreads();

    // compact candidates >= thr (warp-aggregated)
    {
        u64 thr = sh_thr;
        for (int base = 0; base < AA_PAD; base += 1024) {
            int i = base + tid;
            u64 k = (i < AA) ? keys[i] : 0ull;
            bool pred = (i < AA) && (k >= thr);
            unsigned ball = __ballot_sync(0xffffffffu, pred);
            int cnt = __popc(ball);
            int pos0 = 0;
            if (lane == 0 && cnt) pos0 = atomicAdd(&sh_scnt, cnt);
            pos0 = __shfl_sync(0xffffffffu, pos0, 0);
            if (pred) {
                int pos = pos0 + __popc(ball & ((1u << lane) - 1));
                if (pos < CAND) s_sort[pos] = k;
            }
        }
    }
    __syncthreads();

    // descending bitonic sort of 2048 unique keys
    for (int k = 2; k <= CAND; k <<= 1) {
        for (int j = k >> 1; j > 0; j >>= 1) {
            #pragma unroll
            for (int rep = 0; rep < CAND / 1024; rep++) {
                int t = rep * 1024 + tid;
                int ixj = t ^ j;
                if (ixj > t) {
                    u64 x = s_sort[t], y = s_sort[ixj];
                    bool up = ((t & k) == 0);
                    if (up ? (x < y) : (x > y)) { s_sort[t] = y; s_sort[ixj] = x; }
                }
            }
            __syncthreads();
        }
    }

    // gather selected arrays + class counts
    for (int c = tid; c < NCLS; c += 1024) s_cnt[c] = 0;
    __syncthreads();
    int   my_cls = 0;
    {
        u64 key = s_sort[tid];
        float conf = __uint_as_float((unsigned)(key >> 32));
        int a = AA - 1 - (int)(key & 0xFFFFFFFFu);
        const float* p = preds + (size_t)b * 84 * AA;
        float cx = p[0 * AA + a], cy = p[1 * AA + a];
        float w  = p[2 * AA + a], h  = p[3 * AA + a];
        float x1 = cx - 0.5f * w, y1 = cy - 0.5f * h;
        float x2 = cx + 0.5f * w, y2 = cy + 0.5f * h;
        int cls = d_cls[b * AA + a];
        my_cls = cls;
        float sh = (float)cls * 7680.0f;
        int o = b * KTOP + tid;
        d_sel_conf[o] = conf;
        d_sel_cls[o]  = cls;
        d_sel_box[o]  = make_float4(x1, y1, x2, y2);
        d_sel_sbox[o] = make_float4(x1 + sh, y1 + sh, x2 + sh, y2 + sh);
        atomicAdd(&s_cnt[cls], 1);
    }
    __syncthreads();
    if (tid == 0) {
        int acc = 0;
        for (int c = 0; c < NCLS; c++) { s_offs[c] = acc; s_cur[c] = acc; acc += s_cnt[c]; }
        d_nvalid[b] = sh_nvalid;
    }
    __syncthreads();
    {
        int p = atomicAdd(&s_cur[my_cls], 1);
        d_items[b * KTOP + p] = tid;
    }
    for (int c = tid; c < NCLS; c += 1024) {
        d_ccnt[b * NCLS + c] = s_cnt[c];
        d_coff[b * NCLS + c] = s_offs[c];
    }
}

// ---------------- 3. NMS: sparse same-class mask in smem + serial scan ----------------
__global__ void __launch_bounds__(256) nms_kernel() {
    extern __shared__ unsigned s_mask[];          // KTOP*33 words (135168 B)
    __shared__ float4 s_sbox[KTOP];
    __shared__ int s_items[KTOP];
    __shared__ int s_cnt[NCLS], s_offs[NCLS];

    int b = blockIdx.x;
    int tid = threadIdx.x;                        // 256
    int lane = tid & 31;
    int wid  = tid >> 5;

    for (int i = tid; i < KTOP * 33; i += 256) s_mask[i] = 0;
    for (int i = tid; i < KTOP; i += 256) {
        s_sbox[i]  = d_sel_sbox[b * KTOP + i];
        s_items[i] = d_items[b * KTOP + i];
    }
    for (int c = tid; c < NCLS; c += 256) {
        s_cnt[c]  = d_ccnt[b * NCLS + c];
        s_offs[c] = d_coff[b * NCLS + c];
    }
    __syncthreads();

    // cross-class pairs have exactly zero intersection (shift >= 7680 vs coords <= ~800)
    // -> iou == 0 bit-exactly -> only same-class pairs can set bits.
    for (int c = wid; c < NCLS; c += 8) {
        int n = s_cnt[c], off = s_offs[c];
        for (int a2 = 0; a2 < n - 1; a2++) {
            int i = s_items[off + a2];
            float4 bi = s_sbox[i];
            float ai = (bi.z - bi.x) * (bi.w - bi.y);
            for (int b2 = a2 + 1 + lane; b2 < n; b2 += 32) {
                int j = s_items[off + b2];
                float4 bj = s_sbox[j];
                float lx = fmaxf(bi.x, bj.x), ly = fmaxf(bi.y, bj.y);
                float rx = fminf(bi.z, bj.z), ry = fminf(bi.w, bj.w);
                float iw = fmaxf(rx - lx, 0.0f), ih = fmaxf(ry - ly, 0.0f);
                float inter = iw * ih;
                float aj = (bj.z - bj.x) * (bj.w - bj.y);
                float denom = ai + aj - inter + 1e-9f;
                float iou = __fdiv_rn(inter, denom);
                if (iou > 0.45f) {
                    int p = min(i, j), q = max(i, j);
                    atomicOr(&s_mask[p * 33 + (q >> 5)], 1u << (q & 31));
                }
            }
        }
    }
    __syncthreads();

    if (tid >= 32) return;
    int nvalid = d_nvalid[b];

    unsigned vw;                                   // valid bits for items lane*32..+31
    {
        int lo = lane * 32;
        int nv = nvalid - lo;
        vw = (nv >= 32) ? 0xFFFFFFFFu : ((nv <= 0) ? 0u : ((1u << nv) - 1u));
    }

    unsigned acc = 0, keep_local = 0;
    for (int c = 0; c < 32; c++) {
        unsigned base = __shfl_sync(0xffffffffu, acc, c);
        unsigned valc = __shfl_sync(0xffffffffu, vw, c);
        unsigned diag[32];
        #pragma unroll
        for (int j = 0; j < 32; j++) diag[j] = s_mask[(c * 32 + j) * 33 + c];
        unsigned cur = base, kbits = 0;
        #pragma unroll
        for (int j = 0; j < 32; j++) {
            if (((valc >> j) & 1u) && !((cur >> j) & 1u)) {
                cur |= diag[j];
                kbits |= (1u << j);
            }
        }
        unsigned t2 = kbits;
        while (t2) {
            int j = __ffs(t2) - 1; t2 &= t2 - 1;
            acc |= s_mask[(c * 32 + j) * 33 + lane];
        }
        if (lane == c) keep_local = kbits;
    }
    // trim to MAX_DET
    int myc = __popc(keep_local);
    int pre = myc;
    #pragma unroll
    for (int d = 1; d < 32; d <<= 1) {
        int v = __shfl_up_sync(0xffffffffu, pre, d);
        if (lane >= d) pre += v;
    }
    pre -= myc;
    unsigned kw2 = 0, tmp = keep_local;
    while (tmp) {
        int p = __ffs(tmp) - 1; tmp &= tmp - 1;
        int rank = pre + __popc(keep_local & ((1u << p) - 1));
        if (rank < MAX_DET) kw2 |= (1u << p);
    }
    d_keepw[b * KW + lane] = kw2;
}

// ---------------- 4. GT matching + stats ----------------
__global__ void match_kernel(const float* __restrict__ gt_boxes,
                             const int* __restrict__ gt_cls,
                             const int* __restrict__ gt_mask,
                             const int* __restrict__ cat_to_super,
                             float* __restrict__ out) {
    __shared__ u64 sbest[GG];
    __shared__ float4 sgt[GG];
    __shared__ int sgc[GG];
    __shared__ int snpred;
    int b = blockIdx.x;
    int i = threadIdx.x;     // 1024
    if (i < GG) {
        const float* gb = gt_boxes + (size_t)(b * GG + i) * 4;
        sgt[i] = make_float4(gb[0], gb[1], gb[2], gb[3]);
        sgc[i] = gt_cls[b * GG + i];
        sbest[i] = 0ull;
    }
    if (i == 0) snpred = 0;
    __syncthreads();

    bool kb = (d_keepw[b * KW + (i >> 5)] >> (i & 31)) & 1u;
    float conf = d_sel_conf[b * KTOP + i];
    bool pv = kb && (conf > 0.5f);
    float4 bx = d_sel_box[b * KTOP + i];
    int cls = d_sel_cls[b * KTOP + i];

    unsigned ball = __ballot_sync(0xffffffffu, pv);
    if ((i & 31) == 0) atomicAdd(&snpred, __popc(ball));

    float ap = (bx.z - bx.x) * (bx.w - bx.y);
    for (int g = 0; g < GG; g++) {
        float4 gb = sgt[g];
        float lx = fmaxf(bx.x, gb.x), ly = fmaxf(bx.y, gb.y);
        float rx = fminf(bx.z, gb.z), ry = fminf(bx.w, gb.w);
        float iw = fmaxf(rx - lx, 0.0f), ih = fmaxf(ry - ly, 0.0f);
        float inter = iw * ih;
        float ag = (gb.z - gb.x) * (gb.w - gb.y);
        float iou = __fdiv_rn(inter, ap + ag - inter + 1e-9f);
        float ioum = (pv && cls == sgc[g]) ? iou : -1.0f;
        u64 key = ((u64)f2sortable(ioum) << 32) | (unsigned)(KTOP - 1 - i);
        #pragma unroll
        for (int d = 16; d; d >>= 1) {
            u64 o = __shfl_xor_sync(0xffffffffu, key, d);
            if (o > key) key = o;
        }
        if ((i & 31) == 0) atomicMax(&sbest[g], key);
    }
    __syncthreads();

    if (i == 0) {
        float sum_iou = 0.0f, sum_conf = 0.0f;
        int n_hit = 0, n_gt = 0;
        for (int g = 0; g < GG; g++) {
            int gm = gt_mask[b * GG + g];
            if (gm != 0) n_gt++;
            u64 key = sbest[g];
            float biou = sortable2f((unsigned)(key >> 32));
            int pidx = KTOP - 1 - (int)(key & 0xFFFFFFFFu);
            bool hit = (biou > 0.6f) && (gm != 0);
            if (hit) {
                n_hit++;
                sum_iou += biou;
                sum_conf += d_sel_conf[b * KTOP + pidx];
            }
        }
        float fh = (float)n_hit;
        float mean_iou  = __fdiv_rn(sum_iou, fmaxf(fh, 1.0f));
        float mean_conf = (n_hit > 0) ? __fdiv_rn(sum_conf, fmaxf(fh, 1.0f)) : 1.0f;
        float correct   = __fdiv_rn(fh, fmaxf((float)n_gt, 1.0f));

        float cc[NCLS];
        float sc[NSUP];
        for (int c = 0; c < NCLS; c++) cc[c] = 0.0f;
        for (int s = 0; s < NSUP; s++) sc[s] = 0.0f;
        for (int g = 0; g < GG; g++) {
            float gm = (gt_mask[b * GG + g] != 0) ? 1.0f : 0.0f;
            int c = gt_cls[b * GG + g];
            cc[c] += gm;
            sc[cat_to_super[c]] += gm;
        }
        float bc = cc[0]; int mfc = 0;
        for (int c = 1; c < NCLS; c++) if (cc[c] > bc) { bc = cc[c]; mfc = c; }
        float bs = sc[0]; int mfs = 0;
        for (int s = 1; s < NSUP; s++) if (sc[s] > bs) { bs = sc[s]; mfs = s; }

        float r0, r1, r2, r3, r4;
        if (n_gt == 0) {
            if (snpred == 0) { r0 = 1.0f; r1 = 1.0f; r2 = -1.0f; r3 = -1.0f; r4 = 1.0f; }
            else             { r0 = 0.0f; r1 = 1.0f; r2 = -2.0f; r3 = -2.0f; r4 = 0.0f; }
        } else {
            r0 = mean_iou; r1 = mean_conf; r2 = (float)mfc; r3 = (float)mfs; r4 = correct;
        }
        float* o = out + b * 5;
        o[0] = r0; o[1] = r1; o[2] = r2; o[3] = r3; o[4] = r4;
    }
}

// ---------------- launcher ----------------
extern "C" void kernel_launch(void* const* d_in, const int* in_sizes, int n_in,
                              void* d_out, int out_size) {
    const float* preds        = (const float*)d_in[0];
    const float* gt_boxes     = (const float*)d_in[1];
    const int*   gt_cls       = (const int*)d_in[2];
    const int*   gt_mask      = (const int*)d_in[3];
    const int*   cat_to_super = (const int*)d_in[4];
    float* out = (float*)d_out;

    (void)in_sizes; (void)n_in; (void)out_size;

    cudaFuncSetAttribute(nms_kernel, cudaFuncAttributeMaxDynamicSharedMemorySize,
                         KTOP * 33 * (int)sizeof(unsigned));

    init_hist_kernel<<<(BB * NBIN2_PAD + 255) / 256, 256>>>();
    decode_kernel<<<dim3((AA + 255) / 256, BB), 256>>>(preds);
    select_kernel<<<BB, 1024>>>(preds);
    nms_kernel<<<BB, 256, KTOP * 33 * sizeof(unsigned)>>>();
    match_kernel<<<BB, 1024>>>(gt_boxes, gt_cls, gt_mask, cat_to_super, out);
}

// round 7
// speedup vs baseline: 1.9018x; 1.5724x over previous
#include <cuda_runtime.h>
#include <cstdint>

#define BB 32
#define AA 8400
#define AA_PAD 8448
#define NCLS 80
#define KTOP 1024
#define GG 32
#define NSUP 16
#define MAX_DET 300
#define KW (KTOP/32)
#define NBIN2 4098           // bin0 = conf==0, bins 1..4097 = (cbits>>12) - 0x3E800 + 1
#define NBIN2_PAD 4112
#define CAND 2048

typedef unsigned long long u64;

// ---------------- static device scratch ----------------
__device__ u64      d_keys[BB * AA];
__device__ int      d_cls[BB * AA];
__device__ int      d_hist[BB * NBIN2_PAD];
__device__ float    d_sel_conf[BB * KTOP];
__device__ int      d_sel_cls[BB * KTOP];
__device__ float4   d_sel_box[BB * KTOP];
__device__ float4   d_sel_sbox[BB * KTOP];
__device__ unsigned d_keepw[BB * KW];

__device__ __forceinline__ unsigned f2sortable(float f) {
    unsigned b = __float_as_uint(f);
    return (b & 0x80000000u) ? ~b : (b | 0x80000000u);
}
__device__ __forceinline__ float sortable2f(unsigned s) {
    return __uint_as_float((s & 0x80000000u) ? (s ^ 0x80000000u) : ~s);
}

// ---------------- 0. zero histograms ----------------
__global__ void init_hist_kernel() {
    int i = blockIdx.x * blockDim.x + threadIdx.x;
    if (i < BB * NBIN2_PAD) d_hist[i] = 0;
}

// ---------------- 1. decode: conf/cls -> keys + fine histogram ----------------
__global__ void decode_kernel(const float* __restrict__ preds) {
    __shared__ int hh[NBIN2];
    int b = blockIdx.y;
    int a = blockIdx.x * blockDim.x + threadIdx.x;
    for (int i = threadIdx.x; i < NBIN2; i += blockDim.x) hh[i] = 0;
    __syncthreads();
    if (a < AA) {
        const float* p = preds + (size_t)b * 84 * AA;
        float best = p[4 * AA + a];
        int cls = 0;
        #pragma unroll 8
        for (int c = 1; c < NCLS; c++) {
            float v = p[(4 + c) * AA + a];
            if (v > best) { best = v; cls = c; }   // first-max (jnp.argmax)
        }
        float conf = (best > 0.25f) ? best : 0.0f;
        unsigned cbits = __float_as_uint(conf);
        d_keys[b * AA + a] = ((u64)cbits << 32) | (unsigned)(AA - 1 - a);
        d_cls[b * AA + a] = cls;
        int bin = (conf == 0.0f) ? 0 : (int)(cbits >> 12) - 0x3E800 + 1;  // 1..4097
        atomicAdd(&hh[bin], 1);
    }
    __syncthreads();
    for (int i = threadIdx.x; i < NBIN2; i += blockDim.x)
        if (hh[i]) atomicAdd(&d_hist[b * NBIN2_PAD + i], hh[i]);
}

// ---------------- 2. select: suffix-scan cutoff -> compact -> sort -> gather ----------------
#define BINS_PER_T 5
__global__ void __launch_bounds__(1024) select_kernel(const float* __restrict__ preds) {
    __shared__ int  s_hist[NBIN2];
    __shared__ int  s_ps[1024];
    __shared__ u64  s_sort[CAND];
    __shared__ int  sh_cstar, sh_scnt;
    __shared__ u64  sh_thr;

    int b   = blockIdx.x;
    int tid = threadIdx.x;
    int lane = tid & 31;
    const u64* keys = d_keys + (size_t)b * AA;

    for (int i = tid; i < NBIN2; i += 1024) s_hist[i] = d_hist[b * NBIN2_PAD + i];
    if (tid == 0) { sh_cstar = 1; sh_scnt = 0; }
    __syncthreads();

    // partial sums (skip bin 0), then Hillis-Steele suffix scan
    {
        int sum = 0;
        #pragma unroll
        for (int k = 0; k < BINS_PER_T; k++) {
            int c = tid * BINS_PER_T + k;
            if (c >= 1 && c < NBIN2) sum += s_hist[c];
        }
        s_ps[tid] = sum;
    }
    __syncthreads();
    for (int d = 1; d < 1024; d <<= 1) {
        int v = (tid + d < 1024) ? s_ps[tid + d] : 0;
        __syncthreads();
        s_ps[tid] += v;
        __syncthreads();
    }
    // unique firing thread: suffix(me) >= K, suffix(me+1) < K
    {
        int sfx  = s_ps[tid];
        int nxt  = (tid + 1 < 1024) ? s_ps[tid + 1] : 0;
        if (sfx >= KTOP && nxt < KTOP) {
            int cum = nxt, cstar = 1;
            for (int c = min(tid * BINS_PER_T + BINS_PER_T - 1, NBIN2 - 1);
                 c >= tid * BINS_PER_T; c--) {
                if (c < 1) break;
                cum += s_hist[c];
                if (cum >= KTOP) { cstar = c; break; }
            }
            sh_cstar = cstar;
        }
    }
    __syncthreads();
    if (tid == 0) {
        unsigned thrhi = ((unsigned)(sh_cstar - 1 + 0x3E800)) << 12;  // min cbits in bin cstar
        sh_thr = (u64)thrhi << 32;
    }
    for (int i = tid; i < CAND; i += 1024) s_sort[i] = 0ull;
    __syncthreads();

    // compact candidates >= thr (warp-aggregated)
    {
        u64 thr = sh_thr;
        for (int base = 0; base < AA_PAD; base += 1024) {
            int i = base + tid;
            u64 k = (i < AA) ? keys[i] : 0ull;
            bool pred = (i < AA) && (k >= thr);
            unsigned ball = __ballot_sync(0xffffffffu, pred);
            int cnt = __popc(ball);
            int pos0 = 0;
            if (lane == 0 && cnt) pos0 = atomicAdd(&sh_scnt, cnt);
            pos0 = __shfl_sync(0xffffffffu, pos0, 0);
            if (pred) {
                int pos = pos0 + __popc(ball & ((1u << lane) - 1));
                if (pos < CAND) s_sort[pos] = k;
            }
        }
    }
    __syncthreads();

    // descending bitonic sort of 2048 unique keys
    for (int k = 2; k <= CAND; k <<= 1) {
        for (int j = k >> 1; j > 0; j >>= 1) {
            #pragma unroll
            for (int rep = 0; rep < CAND / 1024; rep++) {
                int t = rep * 1024 + tid;
                int ixj = t ^ j;
                if (ixj > t) {
                    u64 x = s_sort[t], y = s_sort[ixj];
                    bool up = ((t & k) == 0);
                    if (up ? (x < y) : (x > y)) { s_sort[t] = y; s_sort[ixj] = x; }
                }
            }
            __syncthreads();
        }
    }

    // gather selected arrays
    {
        u64 key = s_sort[tid];
        float conf = __uint_as_float((unsigned)(key >> 32));
        int a = AA - 1 - (int)(key & 0xFFFFFFFFu);
        const float* p = preds + (size_t)b * 84 * AA;
        float cx = p[0 * AA + a], cy = p[1 * AA + a];
        float w  = p[2 * AA + a], h  = p[3 * AA + a];
        float x1 = cx - 0.5f * w, y1 = cy - 0.5f * h;
        float x2 = cx + 0.5f * w, y2 = cy + 0.5f * h;
        int cls = d_cls[b * AA + a];
        float sh = (float)cls * 7680.0f;
        int o = b * KTOP + tid;
        d_sel_conf[o] = conf;
        d_sel_cls[o]  = cls;
        d_sel_box[o]  = make_float4(x1, y1, x2, y2);
        d_sel_sbox[o] = make_float4(x1 + sh, y1 + sh, x2 + sh, y2 + sh);
    }
}

// ---------------- 3. NMS: per-class warp greedy (no bit-matrix) ----------------
// Cross-class pairs have exactly zero intersection (shift >= 7680 vs coords <= ~800)
// -> iou == 0 bit-exactly -> greedy NMS decomposes per class. Each warp owns
// classes (wid, wid+32, wid+64). Lane l holds the class's remaining-members word
// for rank chunk l. Extract lowest remaining rank (it is KEPT by construction);
// each lane then removes its own members with IOU > 0.45. MAX_DET trim after.
__global__ void __launch_bounds__(1024) nms_kernel() {
    __shared__ float4   s_sbox[KTOP];
    __shared__ float    s_conf[KTOP];
    __shared__ unsigned s_cmask[NCLS * 32];
    __shared__ unsigned s_keep[KW];

    int b = blockIdx.x;
    int tid = threadIdx.x;                     // 1024
    int lane = tid & 31;
    int wid  = tid >> 5;

    for (int i = tid; i < NCLS * 32; i += 1024) s_cmask[i] = 0;
    if (tid < KW) s_keep[tid] = 0;
    s_sbox[tid] = d_sel_sbox[b * KTOP + tid];
    s_conf[tid] = d_sel_conf[b * KTOP + tid];
    __syncthreads();
    {
        int c = d_sel_cls[b * KTOP + tid];
        if (s_conf[tid] > 0.0f)
            atomicOr(&s_cmask[c * 32 + (tid >> 5)], 1u << (tid & 31));
    }
    __syncthreads();

    for (int c = wid; c < NCLS; c += 32) {
        unsigned rem_w = s_cmask[c * 32 + lane];
        while (true) {
            unsigned anyb = __ballot_sync(0xffffffffu, rem_w != 0);
            if (!anyb) break;
            int src = __ffs(anyb) - 1;
            unsigned w0 = __shfl_sync(0xffffffffu, rem_w, src);
            int jb0 = __ffs(w0) - 1;
            int r = src * 32 + jb0;            // lowest remaining rank: KEPT
            if (lane == src) rem_w &= ~(1u << jb0);
            if (lane == 0) atomicOr(&s_keep[r >> 5], 1u << (r & 31));
            float4 bi = s_sbox[r];             // broadcast LDS
            float ai = (bi.z - bi.x) * (bi.w - bi.y);
            unsigned w = rem_w;
            while (w) {
                int jb = __ffs(w) - 1; w &= w - 1;
                float4 bj = s_sbox[lane * 32 + jb];
                float lx = fmaxf(bi.x, bj.x), ly = fmaxf(bi.y, bj.y);
                float rx = fminf(bi.z, bj.z), ry = fminf(bi.w, bj.w);
                float iw = fmaxf(rx - lx, 0.0f), ih = fmaxf(ry - ly, 0.0f);
                float inter = iw * ih;
                float aj = (bj.z - bj.x) * (bj.w - bj.y);
                float denom = ai + aj - inter + 1e-9f;
                float iou = __fdiv_rn(inter, denom);
                if (iou > 0.45f) rem_w &= ~(1u << jb);
            }
        }
    }
    __syncthreads();

    // MAX_DET trim over global rank order (warp 0)
    if (tid < 32) {
        unsigned keep_local = s_keep[lane];
        int myc = __popc(keep_local);
        int pre = myc;
        #pragma unroll
        for (int d = 1; d < 32; d <<= 1) {
            int v = __shfl_up_sync(0xffffffffu, pre, d);
            if (lane >= d) pre += v;
        }
        pre -= myc;
        unsigned kw2 = 0, tmp = keep_local;
        while (tmp) {
            int p = __ffs(tmp) - 1; tmp &= tmp - 1;
            int rank = pre + __popc(keep_local & ((1u << p) - 1));
            if (rank < MAX_DET) kw2 |= (1u << p);
        }
        d_keepw[b * KW + lane] = kw2;
    }
}

// ---------------- 4. GT matching + stats ----------------
__global__ void match_kernel(const float* __restrict__ gt_boxes,
                             const int* __restrict__ gt_cls,
                             const int* __restrict__ gt_mask,
                             const int* __restrict__ cat_to_super,
                             float* __restrict__ out) {
    __shared__ u64 sbest[GG];
    __shared__ float4 sgt[GG];
    __shared__ int sgc[GG];
    __shared__ int snpred;
    int b = blockIdx.x;
    int i = threadIdx.x;     // 1024
    if (i < GG) {
        const float* gb = gt_boxes + (size_t)(b * GG + i) * 4;
        sgt[i] = make_float4(gb[0], gb[1], gb[2], gb[3]);
        sgc[i] = gt_cls[b * GG + i];
        sbest[i] = 0ull;
    }
    if (i == 0) snpred = 0;
    __syncthreads();

    bool kb = (d_keepw[b * KW + (i >> 5)] >> (i & 31)) & 1u;
    float conf = d_sel_conf[b * KTOP + i];
    bool pv = kb && (conf > 0.5f);
    float4 bx = d_sel_box[b * KTOP + i];
    int cls = d_sel_cls[b * KTOP + i];

    unsigned ball = __ballot_sync(0xffffffffu, pv);
    if ((i & 31) == 0) atomicAdd(&snpred, __popc(ball));

    float ap = (bx.z - bx.x) * (bx.w - bx.y);
    for (int g = 0; g < GG; g++) {
        float4 gb = sgt[g];
        float lx = fmaxf(bx.x, gb.x), ly = fmaxf(bx.y, gb.y);
        float rx = fminf(bx.z, gb.z), ry = fminf(bx.w, gb.w);
        float iw = fmaxf(rx - lx, 0.0f), ih = fmaxf(ry - ly, 0.0f);
        float inter = iw * ih;
        float ag = (gb.z - gb.x) * (gb.w - gb.y);
        float iou = __fdiv_rn(inter, ap + ag - inter + 1e-9f);
        float ioum = (pv && cls == sgc[g]) ? iou : -1.0f;
        u64 key = ((u64)f2sortable(ioum) << 32) | (unsigned)(KTOP - 1 - i);
        #pragma unroll
        for (int d = 16; d; d >>= 1) {
            u64 o = __shfl_xor_sync(0xffffffffu, key, d);
            if (o > key) key = o;
        }
        if ((i & 31) == 0) atomicMax(&sbest[g], key);
    }
    __syncthreads();

    if (i == 0) {
        float sum_iou = 0.0f, sum_conf = 0.0f;
        int n_hit = 0, n_gt = 0;
        for (int g = 0; g < GG; g++) {
            int gm = gt_mask[b * GG + g];
            if (gm != 0) n_gt++;
            u64 key = sbest[g];
            float biou = sortable2f((unsigned)(key >> 32));
            int pidx = KTOP - 1 - (int)(key & 0xFFFFFFFFu);
            bool hit = (biou > 0.6f) && (gm != 0);
            if (hit) {
                n_hit++;
                sum_iou += biou;
                sum_conf += d_sel_conf[b * KTOP + pidx];
            }
        }
        float fh = (float)n_hit;
        float mean_iou  = __fdiv_rn(sum_iou, fmaxf(fh, 1.0f));
        float mean_conf = (n_hit > 0) ? __fdiv_rn(sum_conf, fmaxf(fh, 1.0f)) : 1.0f;
        float correct   = __fdiv_rn(fh, fmaxf((float)n_gt, 1.0f));

        float cc[NCLS];
        float sc[NSUP];
        for (int c = 0; c < NCLS; c++) cc[c] = 0.0f;
        for (int s = 0; s < NSUP; s++) sc[s] = 0.0f;
        for (int g = 0; g < GG; g++) {
            float gm = (gt_mask[b * GG + g] != 0) ? 1.0f : 0.0f;
            int c = gt_cls[b * GG + g];
            cc[c] += gm;
            sc[cat_to_super[c]] += gm;
        }
        float bc = cc[0]; int mfc = 0;
        for (int c = 1; c < NCLS; c++) if (cc[c] > bc) { bc = cc[c]; mfc = c; }
        float bs = sc[0]; int mfs = 0;
        for (int s = 1; s < NSUP; s++) if (sc[s] > bs) { bs = sc[s]; mfs = s; }

        float r0, r1, r2, r3, r4;
        if (n_gt == 0) {
            if (snpred == 0) { r0 = 1.0f; r1 = 1.0f; r2 = -1.0f; r3 = -1.0f; r4 = 1.0f; }
            else             { r0 = 0.0f; r1 = 1.0f; r2 = -2.0f; r3 = -2.0f; r4 = 0.0f; }
        } else {
            r0 = mean_iou; r1 = mean_conf; r2 = (float)mfc; r3 = (float)mfs; r4 = correct;
        }
        float* o = out + b * 5;
        o[0] = r0; o[1] = r1; o[2] = r2; o[3] = r3; o[4] = r4;
    }
}

// ---------------- launcher ----------------
extern "C" void kernel_launch(void* const* d_in, const int* in_sizes, int n_in,
                              void* d_out, int out_size) {
    const float* preds        = (const float*)d_in[0];
    const float* gt_boxes     = (const float*)d_in[1];
    const int*   gt_cls       = (const int*)d_in[2];
    const int*   gt_mask      = (const int*)d_in[3];
    const int*   cat_to_super = (const int*)d_in[4];
    float* out = (float*)d_out;

    (void)in_sizes; (void)n_in; (void)out_size;

    init_hist_kernel<<<(BB * NBIN2_PAD + 255) / 256, 256>>>();
    decode_kernel<<<dim3((AA + 255) / 256, BB), 256>>>(preds);
    select_kernel<<<BB, 1024>>>(preds);
    nms_kernel<<<BB, 1024>>>();
    match_kernel<<<BB, 1024>>>(gt_boxes, gt_cls, gt_mask, cat_to_super, out);
}

// round 9
// speedup vs baseline: 2.4041x; 1.2641x over previous
#include <cuda_runtime.h>
#include <cstdint>

#define BB 32
#define AA 8400
#define AA_PAD 8448
#define NCLS 80
#define KTOP 1024
#define GG 32
#define NSUP 16
#define MAX_DET 300
#define KW (KTOP/32)
#define NBIN2 4098           // bin0 = conf==0, bins 1..4097 = (cbits>>12) - 0x3E800 + 1
#define NBIN2_PAD 4112
#define CAND 2048
#define CLS_BLKS 3           // ceil(NCLS/32) blocks of 32 warps: one class per warp

typedef unsigned long long u64;

// ---------------- static device scratch ----------------
__device__ u64      d_keys[BB * AA];
__device__ int      d_cls[BB * AA];
__device__ int      d_hist[BB * NBIN2_PAD];
__device__ float    d_sel_conf[BB * KTOP];
__device__ int      d_sel_cls[BB * KTOP];
__device__ float4   d_sel_box[BB * KTOP];
__device__ float4   d_sel_sbox[BB * KTOP];
__device__ unsigned d_keep[BB * KW];

__device__ __forceinline__ unsigned f2sortable(float f) {
    unsigned b = __float_as_uint(f);
    return (b & 0x80000000u) ? ~b : (b | 0x80000000u);
}
__device__ __forceinline__ float sortable2f(unsigned s) {
    return __uint_as_float((s & 0x80000000u) ? (s ^ 0x80000000u) : ~s);
}

// ---------------- 0. zero histograms + keep words ----------------
__global__ void init_kernel() {
    int i = blockIdx.x * blockDim.x + threadIdx.x;
    if (i < BB * NBIN2_PAD) d_hist[i] = 0;
    if (i < BB * KW) d_keep[i] = 0;
}

// ---------------- 1. decode: conf/cls -> keys + fine histogram ----------------
__global__ void decode_kernel(const float* __restrict__ preds) {
    __shared__ int hh[NBIN2];
    int b = blockIdx.y;
    int a = blockIdx.x * blockDim.x + threadIdx.x;
    for (int i = threadIdx.x; i < NBIN2; i += blockDim.x) hh[i] = 0;
    __syncthreads();
    if (a < AA) {
        const float* p = preds + (size_t)b * 84 * AA;
        float best = p[4 * AA + a];
        int cls = 0;
        #pragma unroll 8
        for (int c = 1; c < NCLS; c++) {
            float v = p[(4 + c) * AA + a];
            if (v > best) { best = v; cls = c; }   // first-max (jnp.argmax)
        }
        float conf = (best > 0.25f) ? best : 0.0f;
        unsigned cbits = __float_as_uint(conf);
        d_keys[b * AA + a] = ((u64)cbits << 32) | (unsigned)(AA - 1 - a);
        d_cls[b * AA + a] = cls;
        int bin = (conf == 0.0f) ? 0 : (int)(cbits >> 12) - 0x3E800 + 1;  // 1..4097
        atomicAdd(&hh[bin], 1);
    }
    __syncthreads();
    for (int i = threadIdx.x; i < NBIN2; i += blockDim.x)
        if (hh[i]) atomicAdd(&d_hist[b * NBIN2_PAD + i], hh[i]);
}

// ---------------- 2. select: suffix-scan cutoff -> compact -> sort -> gather ----------------
#define BINS_PER_T 5
__global__ void __launch_bounds__(1024) select_kernel(const float* __restrict__ preds) {
    __shared__ int  s_hist[NBIN2];
    __shared__ int  s_ps[1024];
    __shared__ u64  s_sort[CAND];
    __shared__ int  sh_cstar, sh_scnt;
    __shared__ u64  sh_thr;

    int b   = blockIdx.x;
    int tid = threadIdx.x;
    int lane = tid & 31;
    const u64* keys = d_keys + (size_t)b * AA;

    for (int i = tid; i < NBIN2; i += 1024) s_hist[i] = d_hist[b * NBIN2_PAD + i];
    if (tid == 0) { sh_cstar = 1; sh_scnt = 0; }
    __syncthreads();

    // partial sums (skip bin 0), then Hillis-Steele suffix scan
    {
        int sum = 0;
        #pragma unroll
        for (int k = 0; k < BINS_PER_T; k++) {
            int c = tid * BINS_PER_T + k;
            if (c >= 1 && c < NBIN2) sum += s_hist[c];
        }
        s_ps[tid] = sum;
    }
    __syncthreads();
    for (int d = 1; d < 1024; d <<= 1) {
        int v = (tid + d < 1024) ? s_ps[tid + d] : 0;
        __syncthreads();
        s_ps[tid] += v;
        __syncthreads();
    }
    // unique firing thread: suffix(me) >= K, suffix(me+1) < K
    {
        int sfx  = s_ps[tid];
        int nxt  = (tid + 1 < 1024) ? s_ps[tid + 1] : 0;
        if (sfx >= KTOP && nxt < KTOP) {
            int cum = nxt, cstar = 1;
            for (int c = min(tid * BINS_PER_T + BINS_PER_T - 1, NBIN2 - 1);
                 c >= tid * BINS_PER_T; c--) {
                if (c < 1) break;
                cum += s_hist[c];
                if (cum >= KTOP) { cstar = c; break; }
            }
            sh_cstar = cstar;
        }
    }
    __syncthreads();
    if (tid == 0) {
        unsigned thrhi = ((unsigned)(sh_cstar - 1 + 0x3E800)) << 12;  // min cbits in bin cstar
        sh_thr = (u64)thrhi << 32;
    }
    for (int i = tid; i < CAND; i += 1024) s_sort[i] = 0ull;
    __syncthreads();

    // compact candidates >= thr (warp-aggregated)
    {
        u64 thr = sh_thr;
        for (int base = 0; base < AA_PAD; base += 1024) {
            int i = base + tid;
            u64 k = (i < AA) ? keys[i] : 0ull;
            bool pred = (i < AA) && (k >= thr);
            unsigned ball = __ballot_sync(0xffffffffu, pred);
            int cnt = __popc(ball);
            int pos0 = 0;
            if (lane == 0 && cnt) pos0 = atomicAdd(&sh_scnt, cnt);
            pos0 = __shfl_sync(0xffffffffu, pos0, 0);
            if (pred) {
                int pos = pos0 + __popc(ball & ((1u << lane) - 1));
                if (pos < CAND) s_sort[pos] = k;
            }
        }
    }
    __syncthreads();

    // descending bitonic sort of 2048 unique keys
    for (int k = 2; k <= CAND; k <<= 1) {
        for (int j = k >> 1; j > 0; j >>= 1) {
            #pragma unroll
            for (int rep = 0; rep < CAND / 1024; rep++) {
                int t = rep * 1024 + tid;
                int ixj = t ^ j;
                if (ixj > t) {
                    u64 x = s_sort[t], y = s_sort[ixj];
                    bool up = ((t & k) == 0);
                    if (up ? (x < y) : (x > y)) { s_sort[t] = y; s_sort[ixj] = x; }
                }
            }
            __syncthreads();
        }
    }

    // gather selected arrays
    {
        u64 key = s_sort[tid];
        float conf = __uint_as_float((unsigned)(key >> 32));
        int a = AA - 1 - (int)(key & 0xFFFFFFFFu);
        const float* p = preds + (size_t)b * 84 * AA;
        float cx = p[0 * AA + a], cy = p[1 * AA + a];
        float w  = p[2 * AA + a], h  = p[3 * AA + a];
        float x1 = cx - 0.5f * w, y1 = cy - 0.5f * h;
        float x2 = cx + 0.5f * w, y2 = cy + 0.5f * h;
        int cls = d_cls[b * AA + a];
        float sh = (float)cls * 7680.0f;
        int o = b * KTOP + tid;
        d_sel_conf[o] = conf;
        d_sel_cls[o]  = cls;
        d_sel_box[o]  = make_float4(x1, y1, x2, y2);
        d_sel_sbox[o] = make_float4(x1 + sh, y1 + sh, x2 + sh, y2 + sh);
    }
}

// ---------------- 3. NMS: one class per WARP, grid (BB, CLS_BLKS) ----------------
// Cross-class IOU is exactly zero (class shift >= 7680 vs coords <= ~800), so greedy
// NMS decomposes per class. Each warp runs one class chain: extract lowest remaining
// rank (kept by construction), lanes kill their own members with IOU > 0.45.
// Boxes read straight from L2 (no smem staging). Keep bits -> global atomicOr.
__global__ void __launch_bounds__(1024) nms_kernel() {
    __shared__ unsigned s_cmask[NCLS * 32];
    int b = blockIdx.x;
    int tid = threadIdx.x;                     // 1024
    int lane = tid & 31;
    int wid  = tid >> 5;

    for (int i = tid; i < NCLS * 32; i += 1024) s_cmask[i] = 0;
    __syncthreads();
    {
        float conf = __ldg(&d_sel_conf[b * KTOP + tid]);
        int c = __ldg(&d_sel_cls[b * KTOP + tid]);
        if (conf > 0.0f)
            atomicOr(&s_cmask[c * 32 + (tid >> 5)], 1u << (tid & 31));
    }
    __syncthreads();

    int c = blockIdx.y * 32 + wid;
    if (c >= NCLS) return;
    const float4* sbox = d_sel_sbox + (size_t)b * KTOP;

    unsigned rem_w = s_cmask[c * 32 + lane];
    unsigned keep_bits = 0;                    // lane l: keep bits of rank chunk l
    while (true) {
        unsigned anyb = __ballot_sync(0xffffffffu, rem_w != 0);
        if (!anyb) break;
        int src = __ffs(anyb) - 1;
        unsigned w0 = __shfl_sync(0xffffffffu, rem_w, src);
        int jb0 = __ffs(w0) - 1;
        int r = src * 32 + jb0;                // lowest remaining rank: KEPT
        if (lane == src) {
            rem_w &= ~(1u << jb0);
            keep_bits |= (1u << jb0);
        }
        float4 bi = __ldg(&sbox[r]);           // uniform address -> broadcast load
        float ai = (bi.z - bi.x) * (bi.w - bi.y);
        unsigned w = rem_w;
        while (w) {
            int jb = __ffs(w) - 1; w &= w - 1;
            float4 bj = __ldg(&sbox[lane * 32 + jb]);
            float lx = fmaxf(bi.x, bj.x), ly = fmaxf(bi.y, bj.y);
            float rx = fminf(bi.z, bj.z), ry = fminf(bi.w, bj.w);
            float iw = fmaxf(rx - lx, 0.0f), ih = fmaxf(ry - ly, 0.0f);
            float inter = iw * ih;
            float aj = (bj.z - bj.x) * (bj.w - bj.y);
            float denom = ai + aj - inter + 1e-9f;
            float iou = __fdiv_rn(inter, denom);
            if (iou > 0.45f) rem_w &= ~(1u << jb);
        }
    }
    if (keep_bits) atomicOr(&d_keep[b * KW + lane], keep_bits);
}

// ---------------- 4. GT matching + stats (with MAX_DET trim prologue) ----------------
__global__ void match_kernel(const float* __restrict__ gt_boxes,
                             const int* __restrict__ gt_cls,
                             const int* __restrict__ gt_mask,
                             const int* __restrict__ cat_to_super,
                             float* __restrict__ out) {
    __shared__ u64 sbest[GG];
    __shared__ float4 sgt[GG];
    __shared__ int sgc[GG];
    __shared__ int snpred;
    __shared__ unsigned s_keepw[KW];
    int b = blockIdx.x;
    int i = threadIdx.x;     // 1024
    int lane = i & 31;

    // trim keep bits to MAX_DET in kept-rank order (warp 0)
    if (i < 32) {
        unsigned keep_local = d_keep[b * KW + lane];
        int myc = __popc(keep_local);
        int pre = myc;
        #pragma unroll
        for (int d = 1; d < 32; d <<= 1) {
            int v = __shfl_up_sync(0xffffffffu, pre, d);
            if (lane >= d) pre += v;
        }
        pre -= myc;
        unsigned kw2 = 0, tmp = keep_local;
        while (tmp) {
            int p = __ffs(tmp) - 1; tmp &= tmp - 1;
            int rank = pre + __popc(keep_local & ((1u << p) - 1));
            if (rank < MAX_DET) kw2 |= (1u << p);
        }
        s_keepw[lane] = kw2;
    }
    if (i < GG) {
        const float* gb = gt_boxes + (size_t)(b * GG + i) * 4;
        sgt[i] = make_float4(gb[0], gb[1], gb[2], gb[3]);
        sgc[i] = gt_cls[b * GG + i];
        sbest[i] = 0ull;
    }
    if (i == 0) snpred = 0;
    __syncthreads();

    bool kb = (s_keepw[i >> 5] >> (i & 31)) & 1u;
    float conf = d_sel_conf[b * KTOP + i];
    bool pv = kb && (conf > 0.5f);
    float4 bx = d_sel_box[b * KTOP + i];
    int cls = d_sel_cls[b * KTOP + i];

    unsigned ball = __ballot_sync(0xffffffffu, pv);
    if (lane == 0) atomicAdd(&snpred, __popc(ball));

    float ap = (bx.z - bx.x) * (bx.w - bx.y);
    for (int g = 0; g < GG; g++) {
        float4 gb = sgt[g];
        float lx = fmaxf(bx.x, gb.x), ly = fmaxf(bx.y, gb.y);
        float rx = fminf(bx.z, gb.z), ry = fminf(bx.w, gb.w);
        float iw = fmaxf(rx - lx, 0.0f), ih = fmaxf(ry - ly, 0.0f);
        float inter = iw * ih;
        float ag = (gb.z - gb.x) * (gb.w - gb.y);
        float iou = __fdiv_rn(inter, ap + ag - inter + 1e-9f);
        float ioum = (pv && cls == sgc[g]) ? iou : -1.0f;
        u64 key = ((u64)f2sortable(ioum) << 32) | (unsigned)(KTOP - 1 - i);
        #pragma unroll
        for (int d = 16; d; d >>= 1) {
            u64 o = __shfl_xor_sync(0xffffffffu, key, d);
            if (o > key) key = o;
        }
        if (lane == 0) atomicMax(&sbest[g], key);
    }
    __syncthreads();

    if (i == 0) {
        float sum_iou = 0.0f, sum_conf = 0.0f;
        int n_hit = 0, n_gt = 0;
        for (int g = 0; g < GG; g++) {
            int gm = gt_mask[b * GG + g];
            if (gm != 0) n_gt++;
            u64 key = sbest[g];
            float biou = sortable2f((unsigned)(key >> 32));
            int pidx = KTOP - 1 - (int)(key & 0xFFFFFFFFu);
            bool hit = (biou > 0.6f) && (gm != 0);
            if (hit) {
                n_hit++;
                sum_iou += biou;
                sum_conf += d_sel_conf[b * KTOP + pidx];
            }
        }
        float fh = (float)n_hit;
        float mean_iou  = __fdiv_rn(sum_iou, fmaxf(fh, 1.0f));
        float mean_conf = (n_hit > 0) ? __fdiv_rn(sum_conf, fmaxf(fh, 1.0f)) : 1.0f;
        float correct   = __fdiv_rn(fh, fmaxf((float)n_gt, 1.0f));

        float cc[NCLS];
        float sc[NSUP];
        for (int c = 0; c < NCLS; c++) cc[c] = 0.0f;
        for (int s = 0; s < NSUP; s++) sc[s] = 0.0f;
        for (int g = 0; g < GG; g++) {
            float gm = (gt_mask[b * GG + g] != 0) ? 1.0f : 0.0f;
            int c = gt_cls[b * GG + g];
            cc[c] += gm;
            sc[cat_to_super[c]] += gm;
        }
        float bc = cc[0]; int mfc = 0;
        for (int c = 1; c < NCLS; c++) if (cc[c] > bc) { bc = cc[c]; mfc = c; }
        float bs = sc[0]; int mfs = 0;
        for (int s = 1; s < NSUP; s++) if (sc[s] > bs) { bs = sc[s]; mfs = s; }

        float r0, r1, r2, r3, r4;
        if (n_gt == 0) {
            if (snpred == 0) { r0 = 1.0f; r1 = 1.0f; r2 = -1.0f; r3 = -1.0f; r4 = 1.0f; }
            else             { r0 = 0.0f; r1 = 1.0f; r2 = -2.0f; r3 = -2.0f; r4 = 0.0f; }
        } else {
            r0 = mean_iou; r1 = mean_conf; r2 = (float)mfc; r3 = (float)mfs; r4 = correct;
        }
        float* o = out + b * 5;
        o[0] = r0; o[1] = r1; o[2] = r2; o[3] = r3; o[4] = r4;
    }
}

// ---------------- launcher ----------------
extern "C" void kernel_launch(void* const* d_in, const int* in_sizes, int n_in,
                              void* d_out, int out_size) {
    const float* preds        = (const float*)d_in[0];
    const float* gt_boxes     = (const float*)d_in[1];
    const int*   gt_cls       = (const int*)d_in[2];
    const int*   gt_mask      = (const int*)d_in[3];
    const int*   cat_to_super = (const int*)d_in[4];
    float* out = (float*)d_out;

    (void)in_sizes; (void)n_in; (void)out_size;

    init_kernel<<<(BB * NBIN2_PAD + 255) / 256, 256>>>();
    decode_kernel<<<dim3((AA + 255) / 256, BB), 256>>>(preds);
    select_kernel<<<BB, 1024>>>(preds);
    nms_kernel<<<dim3(BB, CLS_BLKS), 1024>>>();
    match_kernel<<<BB, 1024>>>(gt_boxes, gt_cls, gt_mask, cat_to_super, out);
}